// round 11
// baseline (speedup 1.0000x reference)
#include <cuda_runtime.h>
#include <cuda_fp16.h>
#include <cstdint>

#define BSZ 64
#define TM 256                      // CTA rows
#define NTHREADS 256
#define STAGE_BYTES 20480           // A 256x32 fp16 (16KB) + B 64x32 fp16 (4KB)
#define NSTAGE 4
#define SMEM_BYTES (NSTAGE * STAGE_BYTES)   // 81920 -> 2 CTAs/SM

#define XN 4096
#define XIN 4096
#define KMAX 1024

// ---------------------------------------------------------------------------
// Device-global scratch (static, no allocations).
// ---------------------------------------------------------------------------
__device__ __half g_xh[(size_t)XN * XIN];          // fp16 x (32MB)
__device__ __half g_bh[(size_t)KMAX * BSZ * BSZ];  // fp16 blocks (8MB)
__device__ int g_start[257];
__device__ int g_list[16384];
__device__ int g_order[256];

// ---------------------------------------------------------------------------
// Fused kernel: block 0 builds CSR (hidden under conversion); blocks 1..G-1
// convert x and blocks f32 -> fp16 (RN).
// ---------------------------------------------------------------------------
__global__ void __launch_bounds__(512)
cvt_and_csr(const float4* __restrict__ xsrc, uint4* __restrict__ xdst, int xn8,
            const float4* __restrict__ bsrc, uint4* __restrict__ bdst, int bn8,
            const int* __restrict__ row_idx, int K, int nrows) {
    if (blockIdx.x == 0) {
        // ---- CSR build: counts, offsets, row-ordered lists, heavy-first order
        __shared__ int s_row[KMAX];
        __shared__ int s_cnt[256];
        __shared__ int s_start[257];
        int tid = threadIdx.x;
        for (int i = tid; i < K; i += 512) s_row[i] = row_idx[i];
        __syncthreads();
        if (tid < nrows) {
            int c = 0;
            for (int j = 0; j < K; j++) c += (s_row[j] == tid) ? 1 : 0;
            s_cnt[tid] = c;
        }
        __syncthreads();
        if (tid == 0) {
            int acc = 0;
            for (int r = 0; r < nrows; r++) { s_start[r] = acc; acc += s_cnt[r]; }
            s_start[nrows] = acc;
        }
        __syncthreads();
        if (tid <= nrows) g_start[tid] = s_start[tid];
        if (tid < nrows) {
            int w = s_start[tid];
            for (int j = 0; j < K; j++)
                if (s_row[j] == tid) g_list[w++] = j;
            // heavy-first order (count desc, row asc)
            int c = s_cnt[tid];
            int rank = 0;
            for (int r2 = 0; r2 < nrows; r2++) {
                int c2 = s_cnt[r2];
                rank += (c2 > c || (c2 == c && r2 < tid)) ? 1 : 0;
            }
            g_order[rank] = tid;
        }
        return;
    }
    // ---- conversion (grid-stride over blocks 1..G-1) ----
    int idx = (blockIdx.x - 1) * blockDim.x + threadIdx.x;
    int stride = (gridDim.x - 1) * blockDim.x;
    int total = xn8 + bn8;
    for (int i = idx; i < total; i += stride) {
        const float4* s; uint4* d; int j;
        if (i < xn8) { s = xsrc; d = xdst; j = i; }
        else         { s = bsrc; d = bdst; j = i - xn8; }
        float4 v0 = s[2 * j];
        float4 v1 = s[2 * j + 1];
        __half2 h0 = __floats2half2_rn(v0.x, v0.y);
        __half2 h1 = __floats2half2_rn(v0.z, v0.w);
        __half2 h2 = __floats2half2_rn(v1.x, v1.y);
        __half2 h3 = __floats2half2_rn(v1.z, v1.w);
        uint4 o;
        o.x = *reinterpret_cast<unsigned*>(&h0);
        o.y = *reinterpret_cast<unsigned*>(&h1);
        o.z = *reinterpret_cast<unsigned*>(&h2);
        o.w = *reinterpret_cast<unsigned*>(&h3);
        d[j] = o;
    }
}

// ---------------------------------------------------------------------------
// helpers
// ---------------------------------------------------------------------------
__device__ __forceinline__ uint32_t smem_to_u32(const void* p) {
    uint32_t a;
    asm("{ .reg .u64 t; cvta.to.shared.u64 t, %1; cvt.u32.u64 %0, t; }" : "=r"(a) : "l"(p));
    return a;
}

#define CP_ASYNC16(dst, src) \
    asm volatile("cp.async.cg.shared.global [%0], [%1], 16;" :: "r"(dst), "l"(src) : "memory")
#define CP_COMMIT() asm volatile("cp.async.commit_group;" ::: "memory")
#define CP_WAIT(n)  asm volatile("cp.async.wait_group %0;" :: "n"(n) : "memory")

#define LDSM_X4(r0, r1, r2, r3, addr) \
    asm volatile("ldmatrix.sync.aligned.m8n8.x4.shared.b16 {%0,%1,%2,%3}, [%4];" \
                 : "=r"(r0), "=r"(r1), "=r"(r2), "=r"(r3) : "r"(addr))

__device__ __forceinline__ void mma_f16(float* c, const unsigned int* a,
                                        unsigned int b0, unsigned int b1) {
    asm volatile(
        "mma.sync.aligned.m16n8k16.row.col.f32.f16.f16.f32 "
        "{%0,%1,%2,%3}, {%4,%5,%6,%7}, {%8,%9}, {%0,%1,%2,%3};\n"
        : "+f"(c[0]), "+f"(c[1]), "+f"(c[2]), "+f"(c[3])
        : "r"(a[0]), "r"(a[1]), "r"(a[2]), "r"(a[3]), "r"(b0), "r"(b1));
}

// ---------------------------------------------------------------------------
// Main GEMM: CTA = (256-row x-tile, 64-col output block row).
// Warp grid 4(M) x 2(N): each warp m64 x n32.
// 4-buffer cp.async ring of K=32 half-stages, 3 stages in flight, one
// __syncthreads per stage. 64B rows, swizzle c' = c ^ ((row>>1)&3).
// ---------------------------------------------------------------------------
__global__ void __launch_bounds__(NTHREADS, 2)
bsl_kernel(const float* __restrict__ bias, const int* __restrict__ col_idx,
           float* __restrict__ y, int IN, int OUT) {
    extern __shared__ float smem[];
    const uint32_t sbase = smem_to_u32(smem);

    const int tid  = threadIdx.x;
    const int lane = tid & 31;
    const int warp = tid >> 5;
    const int wm   = warp & 3;    // 4 warps along M (64 rows each)
    const int wn   = warp >> 2;   // 2 warps along N (32 cols each)
    const int g    = lane >> 2;
    const int t    = lane & 3;

    const int n0   = blockIdx.x * TM;
    const int rblk = g_order[blockIdx.y];
    const int out0 = rblk * BSZ;

    const int beg = g_start[rblk];
    const int cnt = g_start[rblk + 1] - beg;
    const int nst = cnt * 2;

    float acc[4][4][4];
#pragma unroll
    for (int mf = 0; mf < 4; mf++)
#pragma unroll
        for (int nf = 0; nf < 4; nf++)
#pragma unroll
            for (int i = 0; i < 4; i++) acc[mf][nf][i] = 0.0f;

    // ---- ldmatrix lane geometry (64B rows, K=32 per stage -> kk in {0,1}) ----
    const uint32_t a_row = (uint32_t)(wm * 64 + (lane & 15));              // + mf*16
    const uint32_t b_row = (uint32_t)(wn * 32 + (lane & 7) + ((lane >> 4) << 3));
    const uint32_t swa = (a_row >> 1) & 3;   // invariant under +16
    const uint32_t swb = (b_row >> 1) & 3;
    uint32_t cba[2], cbb[2];
#pragma unroll
    for (int kk = 0; kk < 2; kk++) {
        cba[kk] = (uint32_t)(((2 * kk + (lane >> 4)) ^ swa) << 4);
        cbb[kk] = (uint32_t)(((2 * kk + ((lane >> 3) & 1)) ^ swb) << 4);
    }

    // cp.async issue geometry: 16B chunk = 8 fp16; 4 chunks per 64B row
    const int ld_row = tid >> 2;       // +64 per iter
    const int ld_c   = tid & 3;

    // stage s: tile s>>1, k-half s&1
    auto issue_stage = [&](int s) {
        const int k  = g_list[beg + (s >> 1)];
        const int c0 = col_idx[k] * BSZ + (s & 1) * 32;
        const __half* xs = g_xh + (size_t)n0 * IN + c0;
        const __half* bs = g_bh + (size_t)k * (BSZ * BSZ) + (s & 1) * 32;
        const uint32_t buf = sbase + (uint32_t)(s & 3) * STAGE_BYTES;
#pragma unroll
        for (int it = 0; it < 4; it++) {           // A: 1024 chunks (256 rows x 4)
            int row = ld_row + it * 64;
            CP_ASYNC16(buf + (uint32_t)row * 64 + (uint32_t)(((ld_c ^ ((row >> 1) & 3))) << 4),
                       xs + (size_t)row * IN + ld_c * 8);
        }
        {                                           // B: 256 chunks (64 rows x 4)
            int row = ld_row;
            CP_ASYNC16(buf + 16384 + (uint32_t)row * 64 + (uint32_t)(((ld_c ^ ((row >> 1) & 3))) << 4),
                       bs + (size_t)row * BSZ + ld_c * 8);
        }
    };

    // prologue: 3 committed groups (empty if beyond nst)
    if (nst > 0) issue_stage(0);
    CP_COMMIT();
    if (nst > 1) issue_stage(1);
    CP_COMMIT();
    if (nst > 2) issue_stage(2);
    CP_COMMIT();

    for (int s = 0; s < nst; s++) {
        CP_WAIT(2);            // groups issued = s+3; <=2 pending => stage s done
        __syncthreads();       // all warps finished compute of s-1 -> buf (s+3)&3 free
        if (s + 3 < nst) issue_stage(s + 3);
        CP_COMMIT();           // uniform group counting (empty ok)

        const uint32_t buf = sbase + (uint32_t)(s & 3) * STAGE_BYTES;
        const uint32_t ab  = buf + a_row * 64;
        const uint32_t b0b = buf + 16384 + b_row * 64;
        const uint32_t b1b = b0b + 16 * 64;

#pragma unroll
        for (int kk = 0; kk < 2; kk++) {
            unsigned int a[4][4], p[4], q[4];
#pragma unroll
            for (int mf = 0; mf < 4; mf++)
                LDSM_X4(a[mf][0], a[mf][1], a[mf][2], a[mf][3],
                        ab + (uint32_t)(mf * 16 * 64) + cba[kk]);
            LDSM_X4(p[0], p[1], p[2], p[3], b0b + cbb[kk]);   // n 0-15
            LDSM_X4(q[0], q[1], q[2], q[3], b1b + cbb[kk]);   // n 16-31

#pragma unroll
            for (int mf = 0; mf < 4; mf++) {
                mma_f16(acc[mf][0], a[mf], p[0], p[1]);
                mma_f16(acc[mf][1], a[mf], p[2], p[3]);
                mma_f16(acc[mf][2], a[mf], q[0], q[1]);
                mma_f16(acc[mf][3], a[mf], q[2], q[3]);
            }
        }
    }

    // ---- epilogue: y = acc + bias ----
    if (cnt > 0) {
#pragma unroll
        for (int mf = 0; mf < 4; mf++) {
#pragma unroll
            for (int nf = 0; nf < 4; nf++) {
                int row = n0 + wm * 64 + mf * 16 + g;
                int col = out0 + wn * 32 + nf * 8 + 2 * t;
                float2 bv = *reinterpret_cast<const float2*>(bias + col);
                float2 lo, hi;
                lo.x = acc[mf][nf][0] + bv.x;
                lo.y = acc[mf][nf][1] + bv.y;
                hi.x = acc[mf][nf][2] + bv.x;
                hi.y = acc[mf][nf][3] + bv.y;
                *reinterpret_cast<float2*>(y + (size_t)row * OUT + col) = lo;
                *reinterpret_cast<float2*>(y + (size_t)(row + 8) * OUT + col) = hi;
            }
        }
    } else {
        for (int r = warp; r < TM; r += 8) {
            int row = n0 + r;
            float* yrow = y + (size_t)row * OUT + out0;
            for (int c = lane * 2; c < BSZ; c += 64) {
                float2 bv = *reinterpret_cast<const float2*>(bias + out0 + c);
                *reinterpret_cast<float2*>(yrow + c) = bv;
            }
        }
    }
}

// ---------------------------------------------------------------------------
extern "C" void kernel_launch(void* const* d_in, const int* in_sizes, int n_in,
                              void* d_out, int out_size) {
    const float* x      = (const float*)d_in[0];
    const float* blocks = (const float*)d_in[1];
    const float* bias   = (const float*)d_in[2];
    const int*   row_i  = (const int*)d_in[3];
    const int*   col_i  = (const int*)d_in[4];
    float*       y      = (float*)d_out;

    const int K   = in_sizes[3];
    const int OUT = in_sizes[2];
    const int IN  = XIN;
    const int N   = in_sizes[0] / IN;
    const int nrows = OUT / BSZ;

    static __half *xh_ptr = nullptr, *bh_ptr = nullptr;
    if (!xh_ptr) {
        cudaGetSymbolAddress((void**)&xh_ptr, g_xh);
        cudaGetSymbolAddress((void**)&bh_ptr, g_bh);
    }
    // block 0: CSR build; blocks 1..2304: f32->fp16 conversion
    cvt_and_csr<<<2305, 512>>>((const float4*)x, (uint4*)xh_ptr, in_sizes[0] / 8,
                               (const float4*)blocks, (uint4*)bh_ptr, in_sizes[1] / 8,
                               row_i, K, nrows);

    static int attr_set = 0;
    if (!attr_set) {
        cudaFuncSetAttribute(bsl_kernel,
                             cudaFuncAttributeMaxDynamicSharedMemorySize, SMEM_BYTES);
        attr_set = 1;
    }
    dim3 grid(N / TM, nrows);
    bsl_kernel<<<grid, NTHREADS, SMEM_BYTES>>>(bias, col_i, y, IN, OUT);
}

// round 12
// speedup vs baseline: 1.2930x; 1.2930x over previous
#include <cuda_runtime.h>
#include <cuda.h>
#include <cuda_fp16.h>
#include <cstdint>

#define BSZ 64
#define TM 256                      // CTA rows
#define NTHREADS 256
#define STAGE_BYTES 40960           // A 256x64 fp16 (32KB) + B 64x64 fp16 (8KB)
#define SMEM_BYTES (1024 + 2 * STAGE_BYTES)   // mbars + 2 buffers -> 2 CTAs/SM

#define XN 4096
#define XIN 4096
#define KMAX 1024

// ---------------------------------------------------------------------------
// Device-global scratch (static, no allocations).
// ---------------------------------------------------------------------------
__device__ __half g_xh[(size_t)XN * XIN];          // fp16 x (32MB)
__device__ __half g_bh[(size_t)KMAX * BSZ * BSZ];  // fp16 blocks (8MB)
__device__ int g_start[257];
__device__ int g_list[16384];
__device__ int g_order[256];

// ---------------------------------------------------------------------------
// Fused: block 0 builds CSR (hidden under conversion); rest convert f32->fp16.
// ---------------------------------------------------------------------------
__global__ void __launch_bounds__(512)
cvt_and_csr(const float4* __restrict__ xsrc, uint4* __restrict__ xdst, int xn8,
            const float4* __restrict__ bsrc, uint4* __restrict__ bdst, int bn8,
            const int* __restrict__ row_idx, int K, int nrows) {
    if (blockIdx.x == 0) {
        __shared__ int s_row[KMAX];
        __shared__ int s_cnt[256];
        __shared__ int s_start[257];
        int tid = threadIdx.x;
        for (int i = tid; i < K; i += 512) s_row[i] = row_idx[i];
        __syncthreads();
        if (tid < nrows) {
            int c = 0;
            for (int j = 0; j < K; j++) c += (s_row[j] == tid) ? 1 : 0;
            s_cnt[tid] = c;
        }
        __syncthreads();
        if (tid == 0) {
            int acc = 0;
            for (int r = 0; r < nrows; r++) { s_start[r] = acc; acc += s_cnt[r]; }
            s_start[nrows] = acc;
        }
        __syncthreads();
        if (tid <= nrows) g_start[tid] = s_start[tid];
        if (tid < nrows) {
            int w = s_start[tid];
            for (int j = 0; j < K; j++)
                if (s_row[j] == tid) g_list[w++] = j;
            int c = s_cnt[tid];
            int rank = 0;
            for (int r2 = 0; r2 < nrows; r2++) {
                int c2 = s_cnt[r2];
                rank += (c2 > c || (c2 == c && r2 < tid)) ? 1 : 0;
            }
            g_order[rank] = tid;
        }
        return;
    }
    int idx = (blockIdx.x - 1) * blockDim.x + threadIdx.x;
    int stride = (gridDim.x - 1) * blockDim.x;
    int total = xn8 + bn8;
    for (int i = idx; i < total; i += stride) {
        const float4* s; uint4* d; int j;
        if (i < xn8) { s = xsrc; d = xdst; j = i; }
        else         { s = bsrc; d = bdst; j = i - xn8; }
        float4 v0 = s[2 * j];
        float4 v1 = s[2 * j + 1];
        __half2 h0 = __floats2half2_rn(v0.x, v0.y);
        __half2 h1 = __floats2half2_rn(v0.z, v0.w);
        __half2 h2 = __floats2half2_rn(v1.x, v1.y);
        __half2 h3 = __floats2half2_rn(v1.z, v1.w);
        uint4 o;
        o.x = *reinterpret_cast<unsigned*>(&h0);
        o.y = *reinterpret_cast<unsigned*>(&h1);
        o.z = *reinterpret_cast<unsigned*>(&h2);
        o.w = *reinterpret_cast<unsigned*>(&h3);
        d[j] = o;
    }
}

// ---------------------------------------------------------------------------
// helpers
// ---------------------------------------------------------------------------
__device__ __forceinline__ uint32_t smem_to_u32(const void* p) {
    uint32_t a;
    asm("{ .reg .u64 t; cvta.to.shared.u64 t, %1; cvt.u32.u64 %0, t; }" : "=r"(a) : "l"(p));
    return a;
}

#define MBARRIER_INIT(addr, cnt) \
    asm volatile("mbarrier.init.shared.b64 [%0], %1;" :: "r"((uint32_t)(addr)), "r"((uint32_t)(cnt)) : "memory")

#define MBARRIER_EXPECT_TX(addr, bytes) \
    asm volatile("mbarrier.arrive.expect_tx.shared.b64 _, [%0], %1;" \
                 :: "r"((uint32_t)(addr)), "r"((uint32_t)(bytes)) : "memory")

#define MBARRIER_WAIT_PARITY(mbar_smem_addr, phase_parity) do { \
    uint32_t _mbar = (uint32_t)(mbar_smem_addr); \
    uint32_t _parity = (uint32_t)(phase_parity); \
    uint32_t _done; \
    asm volatile("{\n\t.reg .pred p;\n\t" \
        "mbarrier.try_wait.parity.acquire.cta.shared::cta.b64 p, [%1], %2;\n\t" \
        "selp.b32 %0, 1, 0, p;\n\t}" : "=r"(_done) : "r"(_mbar), "r"(_parity) : "memory"); \
    if (!_done) { \
        asm volatile("{\n\t.reg .pred P1;\n\t" \
            "WAIT_LOOP_%=:\n\t" \
            "mbarrier.try_wait.parity.acquire.cta.shared::cta.b64 P1, [%0], %1, 0x989680;\n\t" \
            "@P1 bra.uni WAIT_DONE_%=;\n\t" \
            "bra.uni WAIT_LOOP_%=;\n\t" \
            "WAIT_DONE_%=:\n\t}" :: "r"(_mbar), "r"(_parity) : "memory"); \
    } \
} while (0)

#define TMA_LOAD_2D(smem_addr, map_ptr, cx, cy, mbar) \
    asm volatile("cp.async.bulk.tensor.2d.shared::cta.global.tile.mbarrier::complete_tx::bytes " \
                 "[%0], [%1, {%2, %3}], [%4];" \
                 :: "r"((uint32_t)(smem_addr)), "l"(map_ptr), \
                    "r"((int)(cx)), "r"((int)(cy)), "r"((uint32_t)(mbar)) : "memory")

#define LDSM_X4(r0, r1, r2, r3, addr) \
    asm volatile("ldmatrix.sync.aligned.m8n8.x4.shared.b16 {%0,%1,%2,%3}, [%4];" \
                 : "=r"(r0), "=r"(r1), "=r"(r2), "=r"(r3) : "r"(addr))

__device__ __forceinline__ void mma_f16(float* c, const unsigned int* a,
                                        unsigned int b0, unsigned int b1) {
    asm volatile(
        "mma.sync.aligned.m16n8k16.row.col.f32.f16.f16.f32 "
        "{%0,%1,%2,%3}, {%4,%5,%6,%7}, {%8,%9}, {%0,%1,%2,%3};\n"
        : "+f"(c[0]), "+f"(c[1]), "+f"(c[2]), "+f"(c[3])
        : "r"(a[0]), "r"(a[1]), "r"(a[2]), "r"(a[3]), "r"(b0), "r"(b1));
}

// ---------------------------------------------------------------------------
// Main GEMM: CTA = (256-row x-tile, 64-col output block row).
// TMA (SW128) loads into a 2-stage mbarrier pipeline; fp16 m16n8k16.
// Warp grid 4(M) x 2(N): each warp m64 x n32. 128B smem rows; the ldmatrix
// chunk swizzle (chunk ^ (row&7)) matches TMA SW128 exactly.
// ---------------------------------------------------------------------------
__global__ void __launch_bounds__(NTHREADS, 2)
bsl_kernel(const __grid_constant__ CUtensorMap tma_a,
           const __grid_constant__ CUtensorMap tma_b,
           const float* __restrict__ bias, const int* __restrict__ col_idx,
           float* __restrict__ y, int OUT) {
    extern __shared__ float smem[];
    const uint32_t sbase = smem_to_u32(smem);
    const uint32_t SM_MBAR = sbase;                         // 2 x 8B
    const uint32_t SM_BUF  = (sbase + 1024 + 1023) & ~1023u;

    const int tid  = threadIdx.x;
    const int lane = tid & 31;
    const int warp = tid >> 5;
    const int wm   = warp & 3;    // 4 warps along M (64 rows each)
    const int wn   = warp >> 2;   // 2 warps along N (32 cols each)
    const int g    = lane >> 2;
    const int t    = lane & 3;

    const int n0   = blockIdx.x * TM;
    const int rblk = g_order[blockIdx.y];
    const int out0 = rblk * BSZ;

    const int beg = g_start[rblk];
    const int cnt = g_start[rblk + 1] - beg;

    if (tid == 0) {
        MBARRIER_INIT(SM_MBAR, 1);
        MBARRIER_INIT(SM_MBAR + 8, 1);
    }
    __syncthreads();

    float acc[4][4][4];
#pragma unroll
    for (int mf = 0; mf < 4; mf++)
#pragma unroll
        for (int nf = 0; nf < 4; nf++)
#pragma unroll
            for (int i = 0; i < 4; i++) acc[mf][nf][i] = 0.0f;

    // ---- ldmatrix lane geometry (128B rows, SW128) ----
    const int xo = lane & 7;
    const uint32_t a_row = (uint32_t)(wm * 64 + (lane & 15));             // + mf*16
    const uint32_t b_row = (uint32_t)(wn * 32 + (lane & 7) + ((lane >> 4) << 3));
    uint32_t cba[4], cbb[4];
#pragma unroll
    for (int kk = 0; kk < 4; kk++) {
        cba[kk] = (uint32_t)(((2 * kk + (lane >> 4)) ^ xo) << 4);
        cbb[kk] = (uint32_t)(((2 * kk + ((lane >> 3) & 1)) ^ xo) << 4);
    }

    // stage issuer (tid 0 only): TMA A panel + B block into buf s&1
    auto issue_stage = [&](int s) {
        const int k  = g_list[beg + s];
        const int c0 = col_idx[k] * BSZ;
        const uint32_t buf  = SM_BUF + (uint32_t)(s & 1) * STAGE_BYTES;
        const uint32_t mbar = SM_MBAR + (uint32_t)(s & 1) * 8;
        MBARRIER_EXPECT_TX(mbar, STAGE_BYTES);
        TMA_LOAD_2D(buf,         &tma_a, c0, n0,      mbar);   // A: 256x64
        TMA_LOAD_2D(buf + 32768, &tma_b, 0,  k * BSZ, mbar);   // B: 64x64
    };

    if (tid == 0) {
        if (cnt > 0) issue_stage(0);
        if (cnt > 1) issue_stage(1);
    }

    for (int s = 0; s < cnt; s++) {
        MBARRIER_WAIT_PARITY(SM_MBAR + (uint32_t)(s & 1) * 8, (s >> 1) & 1);

        const uint32_t buf = SM_BUF + (uint32_t)(s & 1) * STAGE_BYTES;
        const uint32_t ab  = buf + a_row * 128;
        const uint32_t b0b = buf + 32768 + b_row * 128;
        const uint32_t b1b = b0b + 16 * 128;

#pragma unroll
        for (int kk = 0; kk < 4; kk++) {
            unsigned int a[4][4], p[4], q[4];
#pragma unroll
            for (int mf = 0; mf < 4; mf++)
                LDSM_X4(a[mf][0], a[mf][1], a[mf][2], a[mf][3],
                        ab + (uint32_t)(mf * 16 * 128) + cba[kk]);
            LDSM_X4(p[0], p[1], p[2], p[3], b0b + cbb[kk]);   // n 0-15
            LDSM_X4(q[0], q[1], q[2], q[3], b1b + cbb[kk]);   // n 16-31

#pragma unroll
            for (int mf = 0; mf < 4; mf++) {
                mma_f16(acc[mf][0], a[mf], p[0], p[1]);
                mma_f16(acc[mf][1], a[mf], p[2], p[3]);
                mma_f16(acc[mf][2], a[mf], q[0], q[1]);
                mma_f16(acc[mf][3], a[mf], q[2], q[3]);
            }
        }
        __syncthreads();                 // all warps done with buf s&1
        if (tid == 0 && s + 2 < cnt) issue_stage(s + 2);
    }

    // ---- epilogue: y = acc + bias ----
    if (cnt > 0) {
#pragma unroll
        for (int mf = 0; mf < 4; mf++) {
#pragma unroll
            for (int nf = 0; nf < 4; nf++) {
                int row = n0 + wm * 64 + mf * 16 + g;
                int col = out0 + wn * 32 + nf * 8 + 2 * t;
                float2 bv = *reinterpret_cast<const float2*>(bias + col);
                float2 lo, hi;
                lo.x = acc[mf][nf][0] + bv.x;
                lo.y = acc[mf][nf][1] + bv.y;
                hi.x = acc[mf][nf][2] + bv.x;
                hi.y = acc[mf][nf][3] + bv.y;
                *reinterpret_cast<float2*>(y + (size_t)row * OUT + col) = lo;
                *reinterpret_cast<float2*>(y + (size_t)(row + 8) * OUT + col) = hi;
            }
        }
    } else {
        for (int r = warp; r < TM; r += 8) {
            int row = n0 + r;
            float* yrow = y + (size_t)row * OUT + out0;
            for (int c = lane * 2; c < BSZ; c += 64) {
                float2 bv = *reinterpret_cast<const float2*>(bias + out0 + c);
                *reinterpret_cast<float2*>(yrow + c) = bv;
            }
        }
    }
}

// ---------------------------------------------------------------------------
extern "C" void kernel_launch(void* const* d_in, const int* in_sizes, int n_in,
                              void* d_out, int out_size) {
    const float* x      = (const float*)d_in[0];
    const float* blocks = (const float*)d_in[1];
    const float* bias   = (const float*)d_in[2];
    const int*   row_i  = (const int*)d_in[3];
    const int*   col_i  = (const int*)d_in[4];
    float*       y      = (float*)d_out;

    const int K   = in_sizes[3];
    const int OUT = in_sizes[2];
    const int IN  = XIN;
    const int N   = in_sizes[0] / IN;
    const int nrows = OUT / BSZ;

    static __half *xh_ptr = nullptr, *bh_ptr = nullptr;
    static CUtensorMap tm_a, tm_b;
    static bool init_done = false;
    if (!init_done) {
        cudaGetSymbolAddress((void**)&xh_ptr, g_xh);
        cudaGetSymbolAddress((void**)&bh_ptr, g_bh);

        typedef CUresult (*EncodeFn)(
            CUtensorMap*, CUtensorMapDataType, cuuint32_t, void*,
            const cuuint64_t*, const cuuint64_t*, const cuuint32_t*,
            const cuuint32_t*, CUtensorMapInterleave, CUtensorMapSwizzle,
            CUtensorMapL2promotion, CUtensorMapFloatOOBfill);
        void* fnp = nullptr;
        cudaDriverEntryPointQueryResult qr;
        cudaGetDriverEntryPoint("cuTensorMapEncodeTiled", &fnp,
                                cudaEnableDefault, &qr);
        EncodeFn encode = (EncodeFn)fnp;

        // A: g_xh as 2D (4096 cols x 4096 rows) fp16, box (64, 256), SW128
        {
            cuuint64_t dims[2]    = {(cuuint64_t)XIN, (cuuint64_t)XN};
            cuuint64_t strides[1] = {(cuuint64_t)XIN * 2};
            cuuint32_t box[2]     = {64, 256};
            cuuint32_t es[2]      = {1, 1};
            encode(&tm_a, CU_TENSOR_MAP_DATA_TYPE_FLOAT16, 2, (void*)xh_ptr,
                   dims, strides, box, es,
                   CU_TENSOR_MAP_INTERLEAVE_NONE, CU_TENSOR_MAP_SWIZZLE_128B,
                   CU_TENSOR_MAP_L2_PROMOTION_L2_128B,
                   CU_TENSOR_MAP_FLOAT_OOB_FILL_NONE);
        }
        // B: g_bh as 2D (64 cols x KMAX*64 rows) fp16, box (64, 64), SW128
        {
            cuuint64_t dims[2]    = {(cuuint64_t)BSZ, (cuuint64_t)KMAX * BSZ};
            cuuint64_t strides[1] = {(cuuint64_t)BSZ * 2};
            cuuint32_t box[2]     = {64, 64};
            cuuint32_t es[2]      = {1, 1};
            encode(&tm_b, CU_TENSOR_MAP_DATA_TYPE_FLOAT16, 2, (void*)bh_ptr,
                   dims, strides, box, es,
                   CU_TENSOR_MAP_INTERLEAVE_NONE, CU_TENSOR_MAP_SWIZZLE_128B,
                   CU_TENSOR_MAP_L2_PROMOTION_L2_128B,
                   CU_TENSOR_MAP_FLOAT_OOB_FILL_NONE);
        }
        cudaFuncSetAttribute(bsl_kernel,
                             cudaFuncAttributeMaxDynamicSharedMemorySize, SMEM_BYTES);
        init_done = true;
    }

    // block 0: CSR build; blocks 1..2304: f32->fp16 conversion
    cvt_and_csr<<<2305, 512>>>((const float4*)x, (uint4*)xh_ptr, in_sizes[0] / 8,
                               (const float4*)blocks, (uint4*)bh_ptr, in_sizes[1] / 8,
                               row_i, K, nrows);

    dim3 grid(N / TM, nrows);
    bsl_kernel<<<grid, NTHREADS, SMEM_BYTES>>>(tm_a, tm_b, bias, col_i, y, OUT);
}